// round 8
// baseline (speedup 1.0000x reference)
#include <cuda_runtime.h>
#include <math.h>

#define HW     16384
#define IMG    128
#define TS     8
#define RAD    5
#define KW     11
#define HALO   18
#define NNB    121
#define SSTR   124
#define KSTR   325
#define WSTRD  128      // global weight row stride
#define SCALE  0.11785113019775793f  // 1/sqrt(72)

typedef unsigned long long ull;

// 8 x HW x 72 buffers + HW x 128 weights
__device__ float g_scratch[HW * (72 * 8) + HW * WSTRD];

__device__ __forceinline__ float gelu_exact(float x) {
    return 0.5f * x * (1.0f + erff(x * 0.70710678118654752f));
}
__device__ __forceinline__ unsigned bf2(float hi, float lo) {
    unsigned r;
    asm("cvt.rn.bf16x2.f32 %0, %1, %2;" : "=r"(r) : "f"(hi), "f"(lo));
    return r;
}
__device__ __forceinline__ float bf_lo(unsigned u) { return __uint_as_float(u << 16); }
__device__ __forceinline__ float bf_hi(unsigned u) { return __uint_as_float(u & 0xffff0000u); }

// ---------------------------------------------------------------------------
// Single GEMM body: Y = X@W + b. 64 px, 288 thr, 4px x 4outs.
// ---------------------------------------------------------------------------
__device__ __forceinline__ void proj_body(const float* __restrict__ X,
                                          const float* __restrict__ W,
                                          const float* __restrict__ B,
                                          float* __restrict__ Y,
                                          int blk, char* smraw) {
    float* Xs = (float*)smraw;        // 64*72
    float* Ws = Xs + 64 * 72;         // 72*72
    float* bs = Ws + 72 * 72;         // 72
    const int tid = threadIdx.x;
    const int pix0 = blk * 64;

    for (int i = tid; i < 64 * 18; i += 288)
        ((float4*)Xs)[i] = ((const float4*)(X + pix0 * 72))[i];
    for (int i = tid; i < 72 * 18; i += 288)
        ((float4*)Ws)[i] = ((const float4*)W)[i];
    if (tid < 72) bs[tid] = B[tid];
    __syncthreads();

    const int og = tid % 18, pg = tid / 18;
    const int ob = og * 4, xb = pg * 4;

    float acc[4][4];
#pragma unroll
    for (int i = 0; i < 4; i++)
#pragma unroll
        for (int j = 0; j < 4; j++) acc[i][j] = 0.0f;

#pragma unroll 3
    for (int k = 0; k < 72; k++) {
        float x0 = Xs[(xb + 0) * 72 + k];
        float x1 = Xs[(xb + 1) * 72 + k];
        float x2 = Xs[(xb + 2) * 72 + k];
        float x3 = Xs[(xb + 3) * 72 + k];
        float4 w = *(const float4*)&Ws[k * 72 + ob];
        acc[0][0] += x0 * w.x; acc[0][1] += x0 * w.y; acc[0][2] += x0 * w.z; acc[0][3] += x0 * w.w;
        acc[1][0] += x1 * w.x; acc[1][1] += x1 * w.y; acc[1][2] += x1 * w.z; acc[1][3] += x1 * w.w;
        acc[2][0] += x2 * w.x; acc[2][1] += x2 * w.y; acc[2][2] += x2 * w.z; acc[2][3] += x2 * w.w;
        acc[3][0] += x3 * w.x; acc[3][1] += x3 * w.y; acc[3][2] += x3 * w.z; acc[3][3] += x3 * w.w;
    }
#pragma unroll
    for (int i = 0; i < 4; i++) {
        float4 r;
        r.x = acc[i][0] + bs[ob + 0];
        r.y = acc[i][1] + bs[ob + 1];
        r.z = acc[i][2] + bs[ob + 2];
        r.w = acc[i][3] + bs[ob + 3];
        *(float4*)&Y[(pix0 + xb + i) * 72 + ob] = r;
    }
}

__global__ __launch_bounds__(288) void proj_quad_kernel(
        const float* __restrict__ X0, const float* __restrict__ W0, const float* __restrict__ B0, float* __restrict__ Y0,
        const float* __restrict__ X1, const float* __restrict__ W1, const float* __restrict__ B1, float* __restrict__ Y1,
        const float* __restrict__ X2, const float* __restrict__ W2, const float* __restrict__ B2, float* __restrict__ Y2,
        const float* __restrict__ X3, const float* __restrict__ W3, const float* __restrict__ B3, float* __restrict__ Y3) {
    __shared__ char smraw[(64 * 72 + 72 * 72 + 72) * 4];
    int g = blockIdx.x >> 8, blk = blockIdx.x & 255;
    const float *X, *W, *B;
    float* Y;
    if (g == 0)      { X = X0; W = W0; B = B0; Y = Y0; }
    else if (g == 1) { X = X1; W = W1; B = B1; Y = Y1; }
    else if (g == 2) { X = X2; W = W2; B = B2; Y = Y2; }
    else             { X = X3; W = W3; B = B3; Y = Y3; }
    proj_body(X, W, B, Y, blk, smraw);
}

__global__ __launch_bounds__(288) void proj_pair_kernel(
        const float* __restrict__ X0, const float* __restrict__ W0, const float* __restrict__ B0, float* __restrict__ Y0,
        const float* __restrict__ X1, const float* __restrict__ W1, const float* __restrict__ B1, float* __restrict__ Y1) {
    __shared__ char smraw[(64 * 72 + 72 * 72 + 72) * 4];
    int g = blockIdx.x >> 8, blk = blockIdx.x & 255;
    const float *X, *W, *B;
    float* Y;
    if (g == 0) { X = X0; W = W0; B = B0; Y = Y0; }
    else        { X = X1; W = W1; B = B1; Y = Y1; }
    proj_body(X, W, B, Y, blk, smraw);
}

// ---------------------------------------------------------------------------
// MLP (gelu) with fused concat: X = [g0+gt (64) | tail (TAIL)]
// ---------------------------------------------------------------------------
template <int TAIL>
__device__ __forceinline__ void mlp_body(const float* __restrict__ g0,
                                         const float* __restrict__ gt,
                                         const float* __restrict__ tail,
                                         const float* __restrict__ W,
                                         const float* __restrict__ B,
                                         float* __restrict__ Y,
                                         int blk, char* smraw) {
    constexpr int DIN = 64 + TAIL;
    float* Xs = (float*)smraw;        // 64*DIN
    float* Ws = Xs + 64 * DIN;        // DIN*72
    float* bs = Ws + DIN * 72;        // 72
    const int tid = threadIdx.x;
    const int pix0 = blk * 64;

    for (int i = tid; i < 64 * 64; i += 288) {
        int p = i >> 6, c = i & 63;
        Xs[p * DIN + c] = g0[(pix0 + p) * 64 + c] + gt[(pix0 + p) * 64 + c];
    }
    for (int i = tid; i < 64 * TAIL; i += 288) {
        int p = i / TAIL, c = i - p * TAIL;
        Xs[p * DIN + 64 + c] = tail[(pix0 + p) * TAIL + c];
    }
    for (int i = tid; i < DIN * 18; i += 288)
        ((float4*)Ws)[i] = ((const float4*)W)[i];
    if (tid < 72) bs[tid] = B[tid];
    __syncthreads();

    const int og = tid % 18, pg = tid / 18;
    const int ob = og * 4, xb = pg * 4;

    float acc[4][4];
#pragma unroll
    for (int i = 0; i < 4; i++)
#pragma unroll
        for (int j = 0; j < 4; j++) acc[i][j] = 0.0f;

#pragma unroll 3
    for (int k = 0; k < DIN; k++) {
        float x0 = Xs[(xb + 0) * DIN + k];
        float x1 = Xs[(xb + 1) * DIN + k];
        float x2 = Xs[(xb + 2) * DIN + k];
        float x3 = Xs[(xb + 3) * DIN + k];
        float4 w = *(const float4*)&Ws[k * 72 + ob];
        acc[0][0] += x0 * w.x; acc[0][1] += x0 * w.y; acc[0][2] += x0 * w.z; acc[0][3] += x0 * w.w;
        acc[1][0] += x1 * w.x; acc[1][1] += x1 * w.y; acc[1][2] += x1 * w.z; acc[1][3] += x1 * w.w;
        acc[2][0] += x2 * w.x; acc[2][1] += x2 * w.y; acc[2][2] += x2 * w.z; acc[2][3] += x2 * w.w;
        acc[3][0] += x3 * w.x; acc[3][1] += x3 * w.y; acc[3][2] += x3 * w.z; acc[3][3] += x3 * w.w;
    }
#pragma unroll
    for (int i = 0; i < 4; i++) {
        float4 r;
        r.x = gelu_exact(acc[i][0] + bs[ob + 0]);
        r.y = gelu_exact(acc[i][1] + bs[ob + 1]);
        r.z = gelu_exact(acc[i][2] + bs[ob + 2]);
        r.w = gelu_exact(acc[i][3] + bs[ob + 3]);
        *(float4*)&Y[(pix0 + xb + i) * 72 + ob] = r;
    }
}

__global__ __launch_bounds__(288) void mlp_pair_kernel(const float* __restrict__ g0,
                                                       const float* __restrict__ gt,
                                                       const float* __restrict__ pi,
                                                       const float* __restrict__ f,
                                                       const float* __restrict__ W1,
                                                       const float* __restrict__ B1,
                                                       const float* __restrict__ W2,
                                                       const float* __restrict__ B2,
                                                       float* __restrict__ Yq,
                                                       float* __restrict__ Ykv) {
    __shared__ char smraw[(64 * 72 + 72 * 72 + 72) * 4];
    if (blockIdx.x < 256) mlp_body<8>(g0, gt, pi, W1, B1, Yq,  blockIdx.x, smraw);
    else                  mlp_body<3>(g0, gt, f,  W2, B2, Ykv, blockIdx.x - 256, smraw);
}

// ---------------------------------------------------------------------------
// Attention stage A: scores + softmax -> normalized weights (f32, global).
// 8x8 tile, 512 threads, 2 blocks/SM. K bf16 channel-pair-major.
// 8 lanes/pixel = 4 neighbor groups x 2 channel halves (q[36] each).
// ---------------------------------------------------------------------------
__global__ __launch_bounds__(512, 2) void attnA_kernel(const float* __restrict__ Q,
                                                       const float* __restrict__ Kp,
                                                       float* __restrict__ Wg) {
    extern __shared__ char smraw[];
    unsigned* Ksh = (unsigned*)smraw;                 // 36 * KSTR (bf16x2)
    float*    S   = (float*)(Ksh + 36 * KSTR);        // 64 * SSTR

    const int tid = threadIdx.x;
    const int tx = blockIdx.x, ty = blockIdx.y;
    const int ox = tx * TS - RAD, oy = ty * TS - RAD;

    for (int i = tid; i < HALO * HALO * 18; i += 512) {
        int cell = i / 18, j = i - cell * 18;
        int hy = cell / HALO, hx = cell - hy * HALO;
        int gy = oy + hy, gx = ox + hx;
        float4 kv = make_float4(0.f, 0.f, 0.f, 0.f);
        if ((unsigned)gy < IMG && (unsigned)gx < IMG)
            kv = __ldg((const float4*)Kp + (gy * IMG + gx) * 18 + j);
        Ksh[(2 * j + 0) * KSTR + cell] = bf2(kv.y, kv.x);
        Ksh[(2 * j + 1) * KSTR + cell] = bf2(kv.w, kv.z);
    }
    __syncthreads();

    const int p = tid >> 3, sub = tid & 7;
    const int half = sub & 1, nn = sub >> 1;
    const int py = p >> 3, px = p & 7;
    const int gy = ty * TS + py, gx = tx * TS + px;

    // ---- phase A: scores (uniform trip counts around the shfl) ----
    {
        float q[36];
        const float4* qr = (const float4*)(Q + (gy * IMG + gx) * 72) + half * 9;
#pragma unroll
        for (int jj = 0; jj < 9; jj++) {
            float4 t = __ldg(qr + jj);
            q[4 * jj + 0] = t.x; q[4 * jj + 1] = t.y;
            q[4 * jj + 2] = t.z; q[4 * jj + 3] = t.w;
        }
        const int j2base = half * 18;
        for (int base = 0; base < 124; base += 4) {
            int n = base + nn;
            bool inrange = (n < NNB);
            int qy = n / 11;
            int qx = n - qy * 11;
            int ny = gy + qy - RAD, nx = gx + qx - RAD;
            bool valid = inrange && ((unsigned)ny < IMG) && ((unsigned)nx < IMG);
            float part = 0.f;
            if (valid) {
                const unsigned* kc = Ksh + (j2base * KSTR) + (py + qy) * HALO + (px + qx);
                float a0 = 0.f, a1 = 0.f, a2 = 0.f, a3 = 0.f;
#pragma unroll
                for (int t2 = 0; t2 < 18; t2 += 2) {
                    unsigned u0 = kc[(t2 + 0) * KSTR];
                    unsigned u1 = kc[(t2 + 1) * KSTR];
                    a0 = fmaf(q[2 * t2 + 0], bf_lo(u0), a0);
                    a1 = fmaf(q[2 * t2 + 1], bf_hi(u0), a1);
                    a2 = fmaf(q[2 * t2 + 2], bf_lo(u1), a2);
                    a3 = fmaf(q[2 * t2 + 3], bf_hi(u1), a3);
                }
                part = (a0 + a1) + (a2 + a3);
            }
            float tot = part + __shfl_xor_sync(0xffffffffu, part, 1);
            if (half == 0 && inrange)
                S[p * SSTR + n] = valid ? tot * SCALE : -INFINITY;
        }
    }
    __syncwarp();

    // ---- softmax + normalized weight writeout ----
    {
        float* row = S + p * SSTR;
        float m = -INFINITY;
        for (int n = sub; n < NNB; n += 8) m = fmaxf(m, row[n]);
        m = fmaxf(m, __shfl_xor_sync(0xffffffffu, m, 1));
        m = fmaxf(m, __shfl_xor_sync(0xffffffffu, m, 2));
        m = fmaxf(m, __shfl_xor_sync(0xffffffffu, m, 4));
        float sum = 0.f;
        for (int n = sub; n < NNB; n += 8) {
            float e = __expf(row[n] - m);
            row[n] = e;
            sum += e;
        }
        sum += __shfl_xor_sync(0xffffffffu, sum, 1);
        sum += __shfl_xor_sync(0xffffffffu, sum, 2);
        sum += __shfl_xor_sync(0xffffffffu, sum, 4);
        float rinv = 1.0f / sum;
        float* wrow = Wg + (gy * IMG + gx) * WSTRD;
        for (int n = sub; n < NNB; n += 8)
            wrow[n] = row[n] * rinv;
    }
}

// ---------------------------------------------------------------------------
// Attention stage B: O = sum_n w_n * V_n. V bf16x4 cell-major, W f32 in smem.
// ---------------------------------------------------------------------------
__global__ __launch_bounds__(512, 2) void attnB_kernel(const float* __restrict__ Wg,
                                                       const float* __restrict__ Vp,
                                                       float* __restrict__ O) {
    extern __shared__ char smraw[];
    ull*   Vsh = (ull*)smraw;                        // 324 * 18 (bf16x4)
    float* Ws  = (float*)(Vsh + HALO * HALO * 18);   // 64 * SSTR

    const int tid = threadIdx.x;
    const int tx = blockIdx.x, ty = blockIdx.y;
    const int ox = tx * TS - RAD, oy = ty * TS - RAD;
    const int pix0y = ty * TS, pix0x = tx * TS;

    for (int i = tid; i < HALO * HALO * 18; i += 512) {
        int cell = i / 18, j = i - cell * 18;
        int hy = cell / HALO, hx = cell - hy * HALO;
        int gy = oy + hy, gx = ox + hx;
        float4 vv = make_float4(0.f, 0.f, 0.f, 0.f);
        if ((unsigned)gy < IMG && (unsigned)gx < IMG)
            vv = __ldg((const float4*)Vp + (gy * IMG + gx) * 18 + j);
        unsigned v01 = bf2(vv.y, vv.x);
        unsigned v23 = bf2(vv.w, vv.z);
        Vsh[cell * 18 + j] = ((ull)v23 << 32) | (ull)v01;
    }
    // weights: 64 px x 121
    for (int i = tid; i < 64 * NNB; i += 512) {
        int p = i / NNB, n = i - p * NNB;
        int gy = pix0y + (p >> 3), gx = pix0x + (p & 7);
        Ws[p * SSTR + n] = __ldg(Wg + (gy * IMG + gx) * WSTRD + n);
    }
    __syncthreads();

    for (int u = tid; u < 64 * 18; u += 512) {
        int pp = u / 18, j = u - pp * 18;
        int ppy = pp >> 3, ppx = pp & 7;
        const float* arow = Ws + pp * SSTR;
        float c0 = 0.f, c1 = 0.f, c2 = 0.f, c3 = 0.f;
#pragma unroll 1
        for (int dy = 0; dy < KW; dy++) {
            const ull* vb = Vsh + (((ppy + dy) * HALO) + ppx) * 18 + j;
            const float* ar = arow + dy * KW;
#pragma unroll
            for (int dx = 0; dx < KW; dx++) {
                float a = ar[dx];
                ull v = vb[dx * 18];
                unsigned u0 = (unsigned)v;
                unsigned u1 = (unsigned)(v >> 32);
                c0 = fmaf(a, bf_lo(u0), c0);
                c1 = fmaf(a, bf_hi(u0), c1);
                c2 = fmaf(a, bf_lo(u1), c2);
                c3 = fmaf(a, bf_hi(u1), c3);
            }
        }
        float4 res = make_float4(c0, c1, c2, c3);
        int ogy = pix0y + ppy, ogx = pix0x + ppx;
        ((float4*)O)[(ogy * IMG + ogx) * 18 + j] = res;
    }
}

// ---------------------------------------------------------------------------
// head (blocks 0..63) + split (blocks 64..)
// ---------------------------------------------------------------------------
__global__ __launch_bounds__(256) void head_split_kernel(const float* __restrict__ gp,
                                                         const float* __restrict__ WG,
                                                         const float* __restrict__ BG,
                                                         const float* __restrict__ WP,
                                                         const float* __restrict__ BP,
                                                         float* __restrict__ out) {
    const int tid = threadIdx.x;
    if (blockIdx.x >= 64) {
        int i = (blockIdx.x - 64) * 256 + tid;
        if (i < HW * 72) {
            int pix = i / 72, c = i - pix * 72;
            float v = gp[i];
            if (c < 64) out[HW * 10 + pix * 64 + c] = v;
            else        out[HW * 74 + pix * 8 + (c - 64)] = v;
        }
        return;
    }
    __shared__ float wg[64 * 7];
    __shared__ float bg[7];
    __shared__ float wp[24];
    __shared__ float bp[3];
    for (int i = tid; i < 448; i += 256) wg[i] = WG[i];
    if (tid < 7)  bg[tid] = BG[tid];
    if (tid < 24) wp[tid] = WP[tid];
    if (tid < 3)  bp[tid] = BP[tid];
    __syncthreads();

    int pix = blockIdx.x * 256 + tid;
    const float* row = gp + pix * 72;

    float gr[7];
#pragma unroll
    for (int j = 0; j < 7; j++) gr[j] = bg[j];
    for (int c = 0; c < 64; c++) {
        float x = row[c];
#pragma unroll
        for (int j = 0; j < 7; j++) gr[j] += x * wg[c * 7 + j];
    }
    float go[7];
#pragma unroll
    for (int j = 0; j < 4; j++) go[j] = 1.0f / (1.0f + __expf(-gr[j]));
    {
        float m = fmaxf(gr[4], fmaxf(gr[5], gr[6]));
        float e0 = __expf(gr[4] - m), e1 = __expf(gr[5] - m), e2 = __expf(gr[6] - m);
        float rs = 1.0f / (e0 + e1 + e2);
        go[4] = e0 * rs; go[5] = e1 * rs; go[6] = e2 * rs;
    }
#pragma unroll
    for (int j = 0; j < 7; j++) out[pix * 7 + j] = go[j];

    float pr[3];
#pragma unroll
    for (int j = 0; j < 3; j++) pr[j] = bp[j];
    for (int c = 0; c < 8; c++) {
        float x = row[64 + c];
#pragma unroll
        for (int j = 0; j < 3; j++) pr[j] += x * wp[c * 3 + j];
    }
    {
        float m = fmaxf(pr[0], fmaxf(pr[1], pr[2]));
        float e0 = __expf(pr[0] - m), e1 = __expf(pr[1] - m), e2 = __expf(pr[2] - m);
        float rs = 1.0f / (e0 + e1 + e2);
        out[HW * 7 + pix * 3 + 0] = e0 * rs;
        out[HW * 7 + pix * 3 + 1] = e1 * rs;
        out[HW * 7 + pix * 3 + 2] = e2 * rs;
    }
}

// ---------------------------------------------------------------------------
extern "C" void kernel_launch(void* const* d_in, const int* in_sizes, int n_in,
                              void* d_out, int out_size) {
    const float* f_t     = (const float*)d_in[0];
    const float* gamma_0 = (const float*)d_in[1];
    const float* gamma_t = (const float*)d_in[2];
    const float* pi_t    = (const float*)d_in[3];
    const float* w_mlp1  = (const float*)d_in[4];
    const float* b_mlp1  = (const float*)d_in[5];
    const float* w_mlp2  = (const float*)d_in[6];
    const float* b_mlp2  = (const float*)d_in[7];
    const float* wq1     = (const float*)d_in[8];
    const float* bq1     = (const float*)d_in[9];
    const float* wk1     = (const float*)d_in[10];
    const float* bk1     = (const float*)d_in[11];
    const float* wv1     = (const float*)d_in[12];
    const float* bv1     = (const float*)d_in[13];
    const float* wq2     = (const float*)d_in[14];
    const float* bq2     = (const float*)d_in[15];
    const float* wk2     = (const float*)d_in[16];
    const float* bk2     = (const float*)d_in[17];
    const float* wv2     = (const float*)d_in[18];
    const float* bv2     = (const float*)d_in[19];
    const float* w_g     = (const float*)d_in[20];
    const float* b_g     = (const float*)d_in[21];
    const float* w_p     = (const float*)d_in[22];
    const float* b_p     = (const float*)d_in[23];
    float* out = (float*)d_out;

    float* base = nullptr;
    cudaGetSymbolAddress((void**)&base, g_scratch);
    float* q   = base;
    float* kv  = q   + HW * 72;
    float* qh1 = kv  + HW * 72;
    float* qh2 = qh1 + HW * 72;
    float* kp  = qh2 + HW * 72;
    float* vp  = kp  + HW * 72;
    float* o1  = vp  + HW * 72;
    float* gp  = o1  + HW * 72;
    float* Wg  = gp  + HW * 72;

    const int attnA_smem = (36 * KSTR) * 4 + (64 * SSTR) * 4;
    const int attnB_smem = (HALO * HALO * 18) * 8 + (64 * SSTR) * 4;
    cudaFuncSetAttribute(attnA_kernel, cudaFuncAttributeMaxDynamicSharedMemorySize, attnA_smem);
    cudaFuncSetAttribute(attnB_kernel, cudaFuncAttributeMaxDynamicSharedMemorySize, attnB_smem);

    mlp_pair_kernel<<<512, 288>>>(gamma_0, gamma_t, pi_t, f_t,
                                  w_mlp1, b_mlp1, w_mlp2, b_mlp2, q, kv);
    proj_quad_kernel<<<1024, 288>>>(q,  wq1, bq1, qh1,
                                    q,  wq2, bq2, qh2,
                                    kv, wk1, bk1, kp,
                                    kv, wv1, bv1, vp);
    attnA_kernel<<<dim3(16, 16), 512, attnA_smem>>>(qh1, kp, Wg);
    attnB_kernel<<<dim3(16, 16), 512, attnB_smem>>>(Wg, vp, o1);
    proj_pair_kernel<<<512, 288>>>(o1, wk2, bk2, kp,
                                   o1, wv2, bv2, vp);
    attnA_kernel<<<dim3(16, 16), 512, attnA_smem>>>(qh2, kp, Wg);
    attnB_kernel<<<dim3(16, 16), 512, attnB_smem>>>(Wg, vp, gp);
    head_split_kernel<<<64 + (HW * 72 + 255) / 256, 256>>>(gp, w_g, b_g, w_p, b_p, out);
}

// round 9
// speedup vs baseline: 1.1699x; 1.1699x over previous
#include <cuda_runtime.h>
#include <math.h>

#define HW     16384
#define IMG    128
#define TS     8
#define RAD    5
#define KW     11
#define HALO   18
#define NNB    121
#define SSTR   124
#define KSTR   325
#define XSTR   76       // padded X row stride in proj smem (bank-conflict-free)
#define SCALE  0.11785113019775793f  // 1/sqrt(72)

typedef unsigned long long ull;

__device__ float g_scratch[HW * 72 * 8];

__device__ __forceinline__ float gelu_exact(float x) {
    return 0.5f * x * (1.0f + erff(x * 0.70710678118654752f));
}
__device__ __forceinline__ unsigned bf2(float hi, float lo) {
    unsigned r;
    asm("cvt.rn.bf16x2.f32 %0, %1, %2;" : "=r"(r) : "f"(hi), "f"(lo));
    return r;
}
__device__ __forceinline__ float bf_lo(unsigned u) { return __uint_as_float(u << 16); }
__device__ __forceinline__ float bf_hi(unsigned u) { return __uint_as_float(u & 0xffff0000u); }

// ---------------------------------------------------------------------------
// Single GEMM body: Y = X@W + b. 64 px, 288 thr, 4px x 4outs.
// Xs padded to stride 76 (conflict-free); k-loop unrolled x3.
// ---------------------------------------------------------------------------
__device__ __forceinline__ void proj_body(const float* __restrict__ X,
                                          const float* __restrict__ W,
                                          const float* __restrict__ B,
                                          float* __restrict__ Y,
                                          int blk, char* smraw) {
    float* Xs = (float*)smraw;        // 64*XSTR
    float* Ws = Xs + 64 * XSTR;       // 72*72
    float* bs = Ws + 72 * 72;         // 72
    const int tid = threadIdx.x;
    const int pix0 = blk * 64;

    for (int i = tid; i < 64 * 18; i += 288) {
        int p = i / 18, c4 = i - p * 18;
        ((float4*)(Xs + p * XSTR))[c4] = ((const float4*)(X + pix0 * 72))[i];
    }
    for (int i = tid; i < 72 * 18; i += 288)
        ((float4*)Ws)[i] = ((const float4*)W)[i];
    if (tid < 72) bs[tid] = B[tid];
    __syncthreads();

    const int og = tid % 18, pg = tid / 18;
    const int ob = og * 4, xb = pg * 4;

    float acc[4][4];
#pragma unroll
    for (int i = 0; i < 4; i++)
#pragma unroll
        for (int j = 0; j < 4; j++) acc[i][j] = 0.0f;

#pragma unroll 3
    for (int k = 0; k < 72; k++) {
        float x0 = Xs[(xb + 0) * XSTR + k];
        float x1 = Xs[(xb + 1) * XSTR + k];
        float x2 = Xs[(xb + 2) * XSTR + k];
        float x3 = Xs[(xb + 3) * XSTR + k];
        float4 w = *(const float4*)&Ws[k * 72 + ob];
        acc[0][0] += x0 * w.x; acc[0][1] += x0 * w.y; acc[0][2] += x0 * w.z; acc[0][3] += x0 * w.w;
        acc[1][0] += x1 * w.x; acc[1][1] += x1 * w.y; acc[1][2] += x1 * w.z; acc[1][3] += x1 * w.w;
        acc[2][0] += x2 * w.x; acc[2][1] += x2 * w.y; acc[2][2] += x2 * w.z; acc[2][3] += x2 * w.w;
        acc[3][0] += x3 * w.x; acc[3][1] += x3 * w.y; acc[3][2] += x3 * w.z; acc[3][3] += x3 * w.w;
    }
#pragma unroll
    for (int i = 0; i < 4; i++) {
        float4 r;
        r.x = acc[i][0] + bs[ob + 0];
        r.y = acc[i][1] + bs[ob + 1];
        r.z = acc[i][2] + bs[ob + 2];
        r.w = acc[i][3] + bs[ob + 3];
        *(float4*)&Y[(pix0 + xb + i) * 72 + ob] = r;
    }
}

__global__ __launch_bounds__(288) void proj_quad_kernel(
        const float* __restrict__ X0, const float* __restrict__ W0, const float* __restrict__ B0, float* __restrict__ Y0,
        const float* __restrict__ X1, const float* __restrict__ W1, const float* __restrict__ B1, float* __restrict__ Y1,
        const float* __restrict__ X2, const float* __restrict__ W2, const float* __restrict__ B2, float* __restrict__ Y2,
        const float* __restrict__ X3, const float* __restrict__ W3, const float* __restrict__ B3, float* __restrict__ Y3) {
    __shared__ char smraw[(64 * XSTR + 72 * 72 + 72) * 4];
    int g = blockIdx.x >> 8, blk = blockIdx.x & 255;
    const float *X, *W, *B;
    float* Y;
    if (g == 0)      { X = X0; W = W0; B = B0; Y = Y0; }
    else if (g == 1) { X = X1; W = W1; B = B1; Y = Y1; }
    else if (g == 2) { X = X2; W = W2; B = B2; Y = Y2; }
    else             { X = X3; W = W3; B = B3; Y = Y3; }
    proj_body(X, W, B, Y, blk, smraw);
}

__global__ __launch_bounds__(288) void proj_pair_kernel(
        const float* __restrict__ X0, const float* __restrict__ W0, const float* __restrict__ B0, float* __restrict__ Y0,
        const float* __restrict__ X1, const float* __restrict__ W1, const float* __restrict__ B1, float* __restrict__ Y1) {
    __shared__ char smraw[(64 * XSTR + 72 * 72 + 72) * 4];
    int g = blockIdx.x >> 8, blk = blockIdx.x & 255;
    const float *X, *W, *B;
    float* Y;
    if (g == 0) { X = X0; W = W0; B = B0; Y = Y0; }
    else        { X = X1; W = W1; B = B1; Y = Y1; }
    proj_body(X, W, B, Y, blk, smraw);
}

// ---------------------------------------------------------------------------
// MLP (gelu) with fused concat: X = [g0+gt (64) | tail (TAIL)], padded stride
// ---------------------------------------------------------------------------
template <int TAIL>
__device__ __forceinline__ void mlp_body(const float* __restrict__ g0,
                                         const float* __restrict__ gt,
                                         const float* __restrict__ tail,
                                         const float* __restrict__ W,
                                         const float* __restrict__ B,
                                         float* __restrict__ Y,
                                         int blk, char* smraw) {
    constexpr int DIN  = 64 + TAIL;
    constexpr int DINP = (TAIL == 8) ? 76 : 68;   // padded stride
    float* Xs = (float*)smraw;        // 64*DINP
    float* Ws = Xs + 64 * DINP;       // DIN*72
    float* bs = Ws + DIN * 72;        // 72
    const int tid = threadIdx.x;
    const int pix0 = blk * 64;

    for (int i = tid; i < 64 * 64; i += 288) {
        int p = i >> 6, c = i & 63;
        Xs[p * DINP + c] = g0[(pix0 + p) * 64 + c] + gt[(pix0 + p) * 64 + c];
    }
    for (int i = tid; i < 64 * TAIL; i += 288) {
        int p = i / TAIL, c = i - p * TAIL;
        Xs[p * DINP + 64 + c] = tail[(pix0 + p) * TAIL + c];
    }
    for (int i = tid; i < DIN * 18; i += 288)
        ((float4*)Ws)[i] = ((const float4*)W)[i];
    if (tid < 72) bs[tid] = B[tid];
    __syncthreads();

    const int og = tid % 18, pg = tid / 18;
    const int ob = og * 4, xb = pg * 4;

    float acc[4][4];
#pragma unroll
    for (int i = 0; i < 4; i++)
#pragma unroll
        for (int j = 0; j < 4; j++) acc[i][j] = 0.0f;

#pragma unroll 3
    for (int k = 0; k < DIN; k++) {
        float x0 = Xs[(xb + 0) * DINP + k];
        float x1 = Xs[(xb + 1) * DINP + k];
        float x2 = Xs[(xb + 2) * DINP + k];
        float x3 = Xs[(xb + 3) * DINP + k];
        float4 w = *(const float4*)&Ws[k * 72 + ob];
        acc[0][0] += x0 * w.x; acc[0][1] += x0 * w.y; acc[0][2] += x0 * w.z; acc[0][3] += x0 * w.w;
        acc[1][0] += x1 * w.x; acc[1][1] += x1 * w.y; acc[1][2] += x1 * w.z; acc[1][3] += x1 * w.w;
        acc[2][0] += x2 * w.x; acc[2][1] += x2 * w.y; acc[2][2] += x2 * w.z; acc[2][3] += x2 * w.w;
        acc[3][0] += x3 * w.x; acc[3][1] += x3 * w.y; acc[3][2] += x3 * w.z; acc[3][3] += x3 * w.w;
    }
#pragma unroll
    for (int i = 0; i < 4; i++) {
        float4 r;
        r.x = gelu_exact(acc[i][0] + bs[ob + 0]);
        r.y = gelu_exact(acc[i][1] + bs[ob + 1]);
        r.z = gelu_exact(acc[i][2] + bs[ob + 2]);
        r.w = gelu_exact(acc[i][3] + bs[ob + 3]);
        *(float4*)&Y[(pix0 + xb + i) * 72 + ob] = r;
    }
}

__global__ __launch_bounds__(288) void mlp_pair_kernel(const float* __restrict__ g0,
                                                       const float* __restrict__ gt,
                                                       const float* __restrict__ pi,
                                                       const float* __restrict__ f,
                                                       const float* __restrict__ W1,
                                                       const float* __restrict__ B1,
                                                       const float* __restrict__ W2,
                                                       const float* __restrict__ B2,
                                                       float* __restrict__ Yq,
                                                       float* __restrict__ Ykv) {
    __shared__ char smraw[(64 * 76 + 72 * 72 + 72) * 4];
    if (blockIdx.x < 256) mlp_body<8>(g0, gt, pi, W1, B1, Yq,  blockIdx.x, smraw);
    else                  mlp_body<3>(g0, gt, f,  W2, B2, Ykv, blockIdx.x - 256, smraw);
}

// ---------------------------------------------------------------------------
// Attention (exact R7 winner): 8x8 tile, 512 threads.
// K bf16 channel-pair-major; V bf16x4 cell-major; overlapped K+V load.
// ---------------------------------------------------------------------------
__global__ __launch_bounds__(512) void attn_kernel(const float* __restrict__ Q,
                                                   const float* __restrict__ Kp,
                                                   const float* __restrict__ Vp,
                                                   float* __restrict__ O) {
    extern __shared__ char smraw[];
    unsigned* Ksh = (unsigned*)smraw;            // 36 * KSTR  (bf16x2 per entry)
    ull*      Vsh = (ull*)(Ksh + 36 * KSTR);     // 324 * 18   (bf16x4 per entry)
    float*    S   = (float*)(Vsh + 324 * 18);    // 64 * SSTR
    float*    red = S + 64 * SSTR;               // 64

    const int tid = threadIdx.x;
    const int tx = blockIdx.x, ty = blockIdx.y;
    const int ox = tx * TS - RAD, oy = ty * TS - RAD;

    for (int i = tid; i < HALO * HALO * 18; i += 512) {
        int cell = i / 18, j = i - cell * 18;
        int hy = cell / HALO, hx = cell - hy * HALO;
        int gy = oy + hy, gx = ox + hx;
        float4 kv = make_float4(0.f, 0.f, 0.f, 0.f);
        float4 vv = kv;
        if ((unsigned)gy < IMG && (unsigned)gx < IMG) {
            int base = (gy * IMG + gx) * 18;
            kv = __ldg((const float4*)Kp + base + j);
            vv = __ldg((const float4*)Vp + base + j);
        }
        Ksh[(2 * j + 0) * KSTR + cell] = bf2(kv.y, kv.x);
        Ksh[(2 * j + 1) * KSTR + cell] = bf2(kv.w, kv.z);
        unsigned v01 = bf2(vv.y, vv.x);
        unsigned v23 = bf2(vv.w, vv.z);
        Vsh[cell * 18 + j] = ((ull)v23 << 32) | (ull)v01;
    }
    __syncthreads();

    const int p = tid >> 3, sub = tid & 7;
    const int py = p >> 3, px = p & 7;
    const int gy = ty * TS + py, gx = tx * TS + px;

    // ---- phase A: scores ----
    {
        float q[72];
        const float4* qr = (const float4*)(Q + (gy * IMG + gx) * 72);
#pragma unroll
        for (int jj = 0; jj < 18; jj++) {
            float4 t = __ldg(qr + jj);
            q[4 * jj + 0] = t.x; q[4 * jj + 1] = t.y;
            q[4 * jj + 2] = t.z; q[4 * jj + 3] = t.w;
        }
        for (int n = sub; n < NNB; n += 8) {
            int qy = n / 11;
            int qx = n - qy * 11;
            int ny = gy + qy - RAD, nx = gx + qx - RAD;
            float s = -INFINITY;
            if ((unsigned)ny < IMG && (unsigned)nx < IMG) {
                const unsigned* kc = Ksh + (py + qy) * HALO + (px + qx);
                float a0 = 0.f, a1 = 0.f, a2 = 0.f, a3 = 0.f;
#pragma unroll
                for (int j2 = 0; j2 < 36; j2 += 2) {
                    unsigned u0 = kc[(j2 + 0) * KSTR];
                    unsigned u1 = kc[(j2 + 1) * KSTR];
                    a0 = fmaf(q[2 * j2 + 0], bf_lo(u0), a0);
                    a1 = fmaf(q[2 * j2 + 1], bf_hi(u0), a1);
                    a2 = fmaf(q[2 * j2 + 2], bf_lo(u1), a2);
                    a3 = fmaf(q[2 * j2 + 3], bf_hi(u1), a3);
                }
                s = (a0 + a1 + a2 + a3) * SCALE;
            }
            S[p * SSTR + n] = s;
        }
    }
    __syncwarp();

    // ---- softmax: 8-lane cooperative ----
    {
        float* row = S + p * SSTR;
        float m = -INFINITY;
        for (int n = sub; n < NNB; n += 8) m = fmaxf(m, row[n]);
        m = fmaxf(m, __shfl_xor_sync(0xffffffffu, m, 1));
        m = fmaxf(m, __shfl_xor_sync(0xffffffffu, m, 2));
        m = fmaxf(m, __shfl_xor_sync(0xffffffffu, m, 4));
        float sum = 0.f;
        for (int n = sub; n < NNB; n += 8) {
            float e = __expf(row[n] - m);
            row[n] = e;
            sum += e;
        }
        sum += __shfl_xor_sync(0xffffffffu, sum, 1);
        sum += __shfl_xor_sync(0xffffffffu, sum, 2);
        sum += __shfl_xor_sync(0xffffffffu, sum, 4);
        if (sub == 0) red[p] = 1.0f / sum;
    }
    __syncthreads();

    // ---- phase B: attn @ V ----
    for (int u = tid; u < 64 * 18; u += 512) {
        int pp = u / 18, j = u - pp * 18;
        int ppy = pp >> 3, ppx = pp & 7;
        const float* arow = S + pp * SSTR;
        float c0 = 0.f, c1 = 0.f, c2 = 0.f, c3 = 0.f;
#pragma unroll 1
        for (int dy = 0; dy < KW; dy++) {
            const ull* vb = Vsh + (((ppy + dy) * HALO) + ppx) * 18 + j;
            const float* ar = arow + dy * KW;
#pragma unroll
            for (int dx = 0; dx < KW; dx++) {
                float a = ar[dx];
                ull v = vb[dx * 18];
                unsigned u0 = (unsigned)v;
                unsigned u1 = (unsigned)(v >> 32);
                c0 = fmaf(a, bf_lo(u0), c0);
                c1 = fmaf(a, bf_hi(u0), c1);
                c2 = fmaf(a, bf_lo(u1), c2);
                c3 = fmaf(a, bf_hi(u1), c3);
            }
        }
        float r = red[pp];
        float4 res = make_float4(c0 * r, c1 * r, c2 * r, c3 * r);
        int ogy = ty * TS + ppy, ogx = tx * TS + ppx;
        ((float4*)O)[(ogy * IMG + ogx) * 18 + j] = res;
    }
}

// ---------------------------------------------------------------------------
// head (blocks 0..63) + split (blocks 64..)
// ---------------------------------------------------------------------------
__global__ __launch_bounds__(256) void head_split_kernel(const float* __restrict__ gp,
                                                         const float* __restrict__ WG,
                                                         const float* __restrict__ BG,
                                                         const float* __restrict__ WP,
                                                         const float* __restrict__ BP,
                                                         float* __restrict__ out) {
    const int tid = threadIdx.x;
    if (blockIdx.x >= 64) {
        int i = (blockIdx.x - 64) * 256 + tid;
        if (i < HW * 72) {
            int pix = i / 72, c = i - pix * 72;
            float v = gp[i];
            if (c < 64) out[HW * 10 + pix * 64 + c] = v;
            else        out[HW * 74 + pix * 8 + (c - 64)] = v;
        }
        return;
    }
    __shared__ float wg[64 * 7];
    __shared__ float bg[7];
    __shared__ float wp[24];
    __shared__ float bp[3];
    for (int i = tid; i < 448; i += 256) wg[i] = WG[i];
    if (tid < 7)  bg[tid] = BG[tid];
    if (tid < 24) wp[tid] = WP[tid];
    if (tid < 3)  bp[tid] = BP[tid];
    __syncthreads();

    int pix = blockIdx.x * 256 + tid;
    const float* row = gp + pix * 72;

    float gr[7];
#pragma unroll
    for (int j = 0; j < 7; j++) gr[j] = bg[j];
    for (int c = 0; c < 64; c++) {
        float x = row[c];
#pragma unroll
        for (int j = 0; j < 7; j++) gr[j] += x * wg[c * 7 + j];
    }
    float go[7];
#pragma unroll
    for (int j = 0; j < 4; j++) go[j] = 1.0f / (1.0f + __expf(-gr[j]));
    {
        float m = fmaxf(gr[4], fmaxf(gr[5], gr[6]));
        float e0 = __expf(gr[4] - m), e1 = __expf(gr[5] - m), e2 = __expf(gr[6] - m);
        float rs = 1.0f / (e0 + e1 + e2);
        go[4] = e0 * rs; go[5] = e1 * rs; go[6] = e2 * rs;
    }
#pragma unroll
    for (int j = 0; j < 7; j++) out[pix * 7 + j] = go[j];

    float pr[3];
#pragma unroll
    for (int j = 0; j < 3; j++) pr[j] = bp[j];
    for (int c = 0; c < 8; c++) {
        float x = row[64 + c];
#pragma unroll
        for (int j = 0; j < 3; j++) pr[j] += x * wp[c * 3 + j];
    }
    {
        float m = fmaxf(pr[0], fmaxf(pr[1], pr[2]));
        float e0 = __expf(pr[0] - m), e1 = __expf(pr[1] - m), e2 = __expf(pr[2] - m);
        float rs = 1.0f / (e0 + e1 + e2);
        out[HW * 7 + pix * 3 + 0] = e0 * rs;
        out[HW * 7 + pix * 3 + 1] = e1 * rs;
        out[HW * 7 + pix * 3 + 2] = e2 * rs;
    }
}

// ---------------------------------------------------------------------------
extern "C" void kernel_launch(void* const* d_in, const int* in_sizes, int n_in,
                              void* d_out, int out_size) {
    const float* f_t     = (const float*)d_in[0];
    const float* gamma_0 = (const float*)d_in[1];
    const float* gamma_t = (const float*)d_in[2];
    const float* pi_t    = (const float*)d_in[3];
    const float* w_mlp1  = (const float*)d_in[4];
    const float* b_mlp1  = (const float*)d_in[5];
    const float* w_mlp2  = (const float*)d_in[6];
    const float* b_mlp2  = (const float*)d_in[7];
    const float* wq1     = (const float*)d_in[8];
    const float* bq1     = (const float*)d_in[9];
    const float* wk1     = (const float*)d_in[10];
    const float* bk1     = (const float*)d_in[11];
    const float* wv1     = (const float*)d_in[12];
    const float* bv1     = (const float*)d_in[13];
    const float* wq2     = (const float*)d_in[14];
    const float* bq2     = (const float*)d_in[15];
    const float* wk2     = (const float*)d_in[16];
    const float* bk2     = (const float*)d_in[17];
    const float* wv2     = (const float*)d_in[18];
    const float* bv2     = (const float*)d_in[19];
    const float* w_g     = (const float*)d_in[20];
    const float* b_g     = (const float*)d_in[21];
    const float* w_p     = (const float*)d_in[22];
    const float* b_p     = (const float*)d_in[23];
    float* out = (float*)d_out;

    float* base = nullptr;
    cudaGetSymbolAddress((void**)&base, g_scratch);
    float* q   = base;
    float* kv  = q   + HW * 72;
    float* qh1 = kv  + HW * 72;
    float* qh2 = qh1 + HW * 72;
    float* kp  = qh2 + HW * 72;
    float* vp  = kp  + HW * 72;
    float* o1  = vp  + HW * 72;
    float* gp  = o1  + HW * 72;

    const int attn_smem = (36 * KSTR) * 4 + (324 * 18) * 8 + (64 * SSTR + 64) * 4;
    cudaFuncSetAttribute(attn_kernel, cudaFuncAttributeMaxDynamicSharedMemorySize, attn_smem);

    mlp_pair_kernel<<<512, 288>>>(gamma_0, gamma_t, pi_t, f_t,
                                  w_mlp1, b_mlp1, w_mlp2, b_mlp2, q, kv);
    proj_quad_kernel<<<1024, 288>>>(q,  wq1, bq1, qh1,
                                    q,  wq2, bq2, qh2,
                                    kv, wk1, bk1, kp,
                                    kv, wv1, bv1, vp);
    attn_kernel<<<dim3(16, 16), 512, attn_smem>>>(qh1, kp, vp, o1);
    proj_pair_kernel<<<512, 288>>>(o1, wk2, bk2, kp,
                                   o1, wv2, bv2, vp);
    attn_kernel<<<dim3(16, 16), 512, attn_smem>>>(qh2, kp, vp, gp);
    head_split_kernel<<<64 + (HW * 72 + 255) / 256, 256>>>(gp, w_g, b_g, w_p, b_p, out);
}

// round 10
// speedup vs baseline: 1.2291x; 1.0506x over previous
#include <cuda_runtime.h>
#include <math.h>

#define HW     16384
#define IMG    128
#define TS     8
#define RAD    5
#define KW     11
#define HALO   18
#define NNB    121
#define SSTR   124
#define KSTR   325
#define SCALE  0.11785113019775793f  // 1/sqrt(72)

typedef unsigned long long ull;

__device__ float g_scratch[HW * 72 * 8];

__device__ __forceinline__ float gelu_exact(float x) {
    return 0.5f * x * (1.0f + erff(x * 0.70710678118654752f));
}
__device__ __forceinline__ unsigned bf2(float hi, float lo) {
    unsigned r;
    asm("cvt.rn.bf16x2.f32 %0, %1, %2;" : "=r"(r) : "f"(hi), "f"(lo));
    return r;
}
__device__ __forceinline__ float bf_lo(unsigned u) { return __uint_as_float(u << 16); }
__device__ __forceinline__ float bf_hi(unsigned u) { return __uint_as_float(u & 0xffff0000u); }

// ---------------------------------------------------------------------------
// Single GEMM body (R7 exact): Y = X@W + b. 64 px, 288 thr, 4px x 4outs.
// ---------------------------------------------------------------------------
__device__ __forceinline__ void proj_body(const float* __restrict__ X,
                                          const float* __restrict__ W,
                                          const float* __restrict__ B,
                                          float* __restrict__ Y,
                                          int blk, char* smraw) {
    float* Xs = (float*)smraw;        // 64*72
    float* Ws = Xs + 64 * 72;         // 72*72
    float* bs = Ws + 72 * 72;         // 72
    const int tid = threadIdx.x;
    const int pix0 = blk * 64;

    for (int i = tid; i < 64 * 18; i += 288)
        ((float4*)Xs)[i] = ((const float4*)(X + pix0 * 72))[i];
    for (int i = tid; i < 72 * 18; i += 288)
        ((float4*)Ws)[i] = ((const float4*)W)[i];
    if (tid < 72) bs[tid] = B[tid];
    __syncthreads();

    const int og = tid % 18, pg = tid / 18;
    const int ob = og * 4, xb = pg * 4;

    float acc[4][4];
#pragma unroll
    for (int i = 0; i < 4; i++)
#pragma unroll
        for (int j = 0; j < 4; j++) acc[i][j] = 0.0f;

    for (int k = 0; k < 72; k++) {
        float x0 = Xs[(xb + 0) * 72 + k];
        float x1 = Xs[(xb + 1) * 72 + k];
        float x2 = Xs[(xb + 2) * 72 + k];
        float x3 = Xs[(xb + 3) * 72 + k];
        float4 w = *(const float4*)&Ws[k * 72 + ob];
        acc[0][0] += x0 * w.x; acc[0][1] += x0 * w.y; acc[0][2] += x0 * w.z; acc[0][3] += x0 * w.w;
        acc[1][0] += x1 * w.x; acc[1][1] += x1 * w.y; acc[1][2] += x1 * w.z; acc[1][3] += x1 * w.w;
        acc[2][0] += x2 * w.x; acc[2][1] += x2 * w.y; acc[2][2] += x2 * w.z; acc[2][3] += x2 * w.w;
        acc[3][0] += x3 * w.x; acc[3][1] += x3 * w.y; acc[3][2] += x3 * w.z; acc[3][3] += x3 * w.w;
    }
#pragma unroll
    for (int i = 0; i < 4; i++) {
        float4 r;
        r.x = acc[i][0] + bs[ob + 0];
        r.y = acc[i][1] + bs[ob + 1];
        r.z = acc[i][2] + bs[ob + 2];
        r.w = acc[i][3] + bs[ob + 3];
        *(float4*)&Y[(pix0 + xb + i) * 72 + ob] = r;
    }
}

__global__ __launch_bounds__(288) void proj_quad_kernel(
        const float* __restrict__ X0, const float* __restrict__ W0, const float* __restrict__ B0, float* __restrict__ Y0,
        const float* __restrict__ X1, const float* __restrict__ W1, const float* __restrict__ B1, float* __restrict__ Y1,
        const float* __restrict__ X2, const float* __restrict__ W2, const float* __restrict__ B2, float* __restrict__ Y2,
        const float* __restrict__ X3, const float* __restrict__ W3, const float* __restrict__ B3, float* __restrict__ Y3) {
    __shared__ char smraw[(64 * 72 + 72 * 72 + 72) * 4];
    int g = blockIdx.x >> 8, blk = blockIdx.x & 255;
    const float *X, *W, *B;
    float* Y;
    if (g == 0)      { X = X0; W = W0; B = B0; Y = Y0; }
    else if (g == 1) { X = X1; W = W1; B = B1; Y = Y1; }
    else if (g == 2) { X = X2; W = W2; B = B2; Y = Y2; }
    else             { X = X3; W = W3; B = B3; Y = Y3; }
    proj_body(X, W, B, Y, blk, smraw);
}

__global__ __launch_bounds__(288) void proj_pair_kernel(
        const float* __restrict__ X0, const float* __restrict__ W0, const float* __restrict__ B0, float* __restrict__ Y0,
        const float* __restrict__ X1, const float* __restrict__ W1, const float* __restrict__ B1, float* __restrict__ Y1) {
    __shared__ char smraw[(64 * 72 + 72 * 72 + 72) * 4];
    int g = blockIdx.x >> 8, blk = blockIdx.x & 255;
    const float *X, *W, *B;
    float* Y;
    if (g == 0) { X = X0; W = W0; B = B0; Y = Y0; }
    else        { X = X1; W = W1; B = B1; Y = Y1; }
    proj_body(X, W, B, Y, blk, smraw);
}

// ---------------------------------------------------------------------------
// MLP (gelu) with fused concat (R7 exact)
// ---------------------------------------------------------------------------
template <int TAIL>
__device__ __forceinline__ void mlp_body(const float* __restrict__ g0,
                                         const float* __restrict__ gt,
                                         const float* __restrict__ tail,
                                         const float* __restrict__ W,
                                         const float* __restrict__ B,
                                         float* __restrict__ Y,
                                         int blk, char* smraw) {
    constexpr int DIN = 64 + TAIL;
    float* Xs = (float*)smraw;        // 64*DIN
    float* Ws = Xs + 64 * DIN;        // DIN*72
    float* bs = Ws + DIN * 72;        // 72
    const int tid = threadIdx.x;
    const int pix0 = blk * 64;

    for (int i = tid; i < 64 * 64; i += 288) {
        int p = i >> 6, c = i & 63;
        Xs[p * DIN + c] = g0[(pix0 + p) * 64 + c] + gt[(pix0 + p) * 64 + c];
    }
    for (int i = tid; i < 64 * TAIL; i += 288) {
        int p = i / TAIL, c = i - p * TAIL;
        Xs[p * DIN + 64 + c] = tail[(pix0 + p) * TAIL + c];
    }
    for (int i = tid; i < DIN * 18; i += 288)
        ((float4*)Ws)[i] = ((const float4*)W)[i];
    if (tid < 72) bs[tid] = B[tid];
    __syncthreads();

    const int og = tid % 18, pg = tid / 18;
    const int ob = og * 4, xb = pg * 4;

    float acc[4][4];
#pragma unroll
    for (int i = 0; i < 4; i++)
#pragma unroll
        for (int j = 0; j < 4; j++) acc[i][j] = 0.0f;

    for (int k = 0; k < DIN; k++) {
        float x0 = Xs[(xb + 0) * DIN + k];
        float x1 = Xs[(xb + 1) * DIN + k];
        float x2 = Xs[(xb + 2) * DIN + k];
        float x3 = Xs[(xb + 3) * DIN + k];
        float4 w = *(const float4*)&Ws[k * 72 + ob];
        acc[0][0] += x0 * w.x; acc[0][1] += x0 * w.y; acc[0][2] += x0 * w.z; acc[0][3] += x0 * w.w;
        acc[1][0] += x1 * w.x; acc[1][1] += x1 * w.y; acc[1][2] += x1 * w.z; acc[1][3] += x1 * w.w;
        acc[2][0] += x2 * w.x; acc[2][1] += x2 * w.y; acc[2][2] += x2 * w.z; acc[2][3] += x2 * w.w;
        acc[3][0] += x3 * w.x; acc[3][1] += x3 * w.y; acc[3][2] += x3 * w.z; acc[3][3] += x3 * w.w;
    }
#pragma unroll
    for (int i = 0; i < 4; i++) {
        float4 r;
        r.x = gelu_exact(acc[i][0] + bs[ob + 0]);
        r.y = gelu_exact(acc[i][1] + bs[ob + 1]);
        r.z = gelu_exact(acc[i][2] + bs[ob + 2]);
        r.w = gelu_exact(acc[i][3] + bs[ob + 3]);
        *(float4*)&Y[(pix0 + xb + i) * 72 + ob] = r;
    }
}

__global__ __launch_bounds__(288) void mlp_pair_kernel(const float* __restrict__ g0,
                                                       const float* __restrict__ gt,
                                                       const float* __restrict__ pi,
                                                       const float* __restrict__ f,
                                                       const float* __restrict__ W1,
                                                       const float* __restrict__ B1,
                                                       const float* __restrict__ W2,
                                                       const float* __restrict__ B2,
                                                       float* __restrict__ Yq,
                                                       float* __restrict__ Ykv) {
    __shared__ char smraw[(64 * 72 + 72 * 72 + 72) * 4];
    if (blockIdx.x < 256) mlp_body<8>(g0, gt, pi, W1, B1, Yq,  blockIdx.x, smraw);
    else                  mlp_body<3>(g0, gt, f,  W2, B2, Ykv, blockIdx.x - 256, smraw);
}

// ---------------------------------------------------------------------------
// Attention: 8x8 tile, 1024 threads (32 warps, 1 block/SM).
// 16 lanes/pixel = 8 neighbor groups x 2 channel halves (q[36] each).
// K bf16 channel-pair-major; V bf16x4 cell-major; overlapped K+V load.
// ---------------------------------------------------------------------------
__global__ __launch_bounds__(1024) void attn_kernel(const float* __restrict__ Q,
                                                    const float* __restrict__ Kp,
                                                    const float* __restrict__ Vp,
                                                    float* __restrict__ O) {
    extern __shared__ char smraw[];
    unsigned* Ksh = (unsigned*)smraw;            // 36 * KSTR  (bf16x2 per entry)
    ull*      Vsh = (ull*)(Ksh + 36 * KSTR);     // 324 * 18   (bf16x4 per entry)
    float*    S   = (float*)(Vsh + 324 * 18);    // 64 * SSTR
    float*    red = S + 64 * SSTR;               // 64

    const int tid = threadIdx.x;
    const int tx = blockIdx.x, ty = blockIdx.y;
    const int ox = tx * TS - RAD, oy = ty * TS - RAD;

    for (int i = tid; i < HALO * HALO * 18; i += 1024) {
        int cell = i / 18, j = i - cell * 18;
        int hy = cell / HALO, hx = cell - hy * HALO;
        int gy = oy + hy, gx = ox + hx;
        float4 kv = make_float4(0.f, 0.f, 0.f, 0.f);
        float4 vv = kv;
        if ((unsigned)gy < IMG && (unsigned)gx < IMG) {
            int base = (gy * IMG + gx) * 18;
            kv = __ldg((const float4*)Kp + base + j);
            vv = __ldg((const float4*)Vp + base + j);
        }
        Ksh[(2 * j + 0) * KSTR + cell] = bf2(kv.y, kv.x);
        Ksh[(2 * j + 1) * KSTR + cell] = bf2(kv.w, kv.z);
        unsigned v01 = bf2(vv.y, vv.x);
        unsigned v23 = bf2(vv.w, vv.z);
        Vsh[cell * 18 + j] = ((ull)v23 << 32) | (ull)v01;
    }
    __syncthreads();

    const int p = tid >> 4, sub = tid & 15;     // 64 px x 16 lanes
    const int half = sub & 1, nn = sub >> 1;    // 2 halves x 8 groups
    const int py = p >> 3, px = p & 7;
    const int gy = ty * TS + py, gx = tx * TS + px;

    // ---- phase A: scores (uniform 16 iterations around the shfl) ----
    {
        float q[36];
        const float4* qr = (const float4*)(Q + (gy * IMG + gx) * 72) + half * 9;
#pragma unroll
        for (int jj = 0; jj < 9; jj++) {
            float4 t = __ldg(qr + jj);
            q[4 * jj + 0] = t.x; q[4 * jj + 1] = t.y;
            q[4 * jj + 2] = t.z; q[4 * jj + 3] = t.w;
        }
        const int j2base = half * 18;
        for (int base = 0; base < 128; base += 8) {
            int n = base + nn;                 // 0..127
            bool inrange = (n < NNB);
            int qy = n / 11;
            int qx = n - qy * 11;
            int ny = gy + qy - RAD, nx = gx + qx - RAD;
            bool valid = inrange && ((unsigned)ny < IMG) && ((unsigned)nx < IMG);
            float part = 0.f;
            if (valid) {
                const unsigned* kc = Ksh + (j2base * KSTR) + (py + qy) * HALO + (px + qx);
                float a0 = 0.f, a1 = 0.f, a2 = 0.f, a3 = 0.f;
#pragma unroll
                for (int t2 = 0; t2 < 18; t2 += 2) {
                    unsigned u0 = kc[(t2 + 0) * KSTR];
                    unsigned u1 = kc[(t2 + 1) * KSTR];
                    a0 = fmaf(q[2 * t2 + 0], bf_lo(u0), a0);
                    a1 = fmaf(q[2 * t2 + 1], bf_hi(u0), a1);
                    a2 = fmaf(q[2 * t2 + 2], bf_lo(u1), a2);
                    a3 = fmaf(q[2 * t2 + 3], bf_hi(u1), a3);
                }
                part = (a0 + a1) + (a2 + a3);
            }
            float tot = part + __shfl_xor_sync(0xffffffffu, part, 1);
            if (half == 0 && inrange)
                S[p * SSTR + n] = valid ? tot * SCALE : -INFINITY;
        }
    }
    __syncwarp();

    // ---- softmax: 16-lane cooperative (shfls outside loops) ----
    {
        float* row = S + p * SSTR;
        float m = -INFINITY;
        for (int n = sub; n < NNB; n += 16) m = fmaxf(m, row[n]);
        m = fmaxf(m, __shfl_xor_sync(0xffffffffu, m, 1));
        m = fmaxf(m, __shfl_xor_sync(0xffffffffu, m, 2));
        m = fmaxf(m, __shfl_xor_sync(0xffffffffu, m, 4));
        m = fmaxf(m, __shfl_xor_sync(0xffffffffu, m, 8));
        float sum = 0.f;
        for (int n = sub; n < NNB; n += 16) {
            float e = __expf(row[n] - m);
            row[n] = e;
            sum += e;
        }
        sum += __shfl_xor_sync(0xffffffffu, sum, 1);
        sum += __shfl_xor_sync(0xffffffffu, sum, 2);
        sum += __shfl_xor_sync(0xffffffffu, sum, 4);
        sum += __shfl_xor_sync(0xffffffffu, sum, 8);
        if (sub == 0) red[p] = 1.0f / sum;
    }
    __syncthreads();

    // ---- phase B: attn @ V ----
    for (int u = tid; u < 64 * 18; u += 1024) {
        int pp = u / 18, j = u - pp * 18;
        int ppy = pp >> 3, ppx = pp & 7;
        const float* arow = S + pp * SSTR;
        float c0 = 0.f, c1 = 0.f, c2 = 0.f, c3 = 0.f;
#pragma unroll 1
        for (int dy = 0; dy < KW; dy++) {
            const ull* vb = Vsh + (((ppy + dy) * HALO) + ppx) * 18 + j;
            const float* ar = arow + dy * KW;
#pragma unroll
            for (int dx = 0; dx < KW; dx++) {
                float a = ar[dx];
                ull v = vb[dx * 18];
                unsigned u0 = (unsigned)v;
                unsigned u1 = (unsigned)(v >> 32);
                c0 = fmaf(a, bf_lo(u0), c0);
                c1 = fmaf(a, bf_hi(u0), c1);
                c2 = fmaf(a, bf_lo(u1), c2);
                c3 = fmaf(a, bf_hi(u1), c3);
            }
        }
        float r = red[pp];
        float4 res = make_float4(c0 * r, c1 * r, c2 * r, c3 * r);
        int ogy = ty * TS + ppy, ogx = tx * TS + ppx;
        ((float4*)O)[(ogy * IMG + ogx) * 18 + j] = res;
    }
}

// ---------------------------------------------------------------------------
// head (blocks 0..63) + split (blocks 64..)
// ---------------------------------------------------------------------------
__global__ __launch_bounds__(256) void head_split_kernel(const float* __restrict__ gp,
                                                         const float* __restrict__ WG,
                                                         const float* __restrict__ BG,
                                                         const float* __restrict__ WP,
                                                         const float* __restrict__ BP,
                                                         float* __restrict__ out) {
    const int tid = threadIdx.x;
    if (blockIdx.x >= 64) {
        int i = (blockIdx.x - 64) * 256 + tid;
        if (i < HW * 72) {
            int pix = i / 72, c = i - pix * 72;
            float v = gp[i];
            if (c < 64) out[HW * 10 + pix * 64 + c] = v;
            else        out[HW * 74 + pix * 8 + (c - 64)] = v;
        }
        return;
    }
    __shared__ float wg[64 * 7];
    __shared__ float bg[7];
    __shared__ float wp[24];
    __shared__ float bp[3];
    for (int i = tid; i < 448; i += 256) wg[i] = WG[i];
    if (tid < 7)  bg[tid] = BG[tid];
    if (tid < 24) wp[tid] = WP[tid];
    if (tid < 3)  bp[tid] = BP[tid];
    __syncthreads();

    int pix = blockIdx.x * 256 + tid;
    const float* row = gp + pix * 72;

    float gr[7];
#pragma unroll
    for (int j = 0; j < 7; j++) gr[j] = bg[j];
    for (int c = 0; c < 64; c++) {
        float x = row[c];
#pragma unroll
        for (int j = 0; j < 7; j++) gr[j] += x * wg[c * 7 + j];
    }
    float go[7];
#pragma unroll
    for (int j = 0; j < 4; j++) go[j] = 1.0f / (1.0f + __expf(-gr[j]));
    {
        float m = fmaxf(gr[4], fmaxf(gr[5], gr[6]));
        float e0 = __expf(gr[4] - m), e1 = __expf(gr[5] - m), e2 = __expf(gr[6] - m);
        float rs = 1.0f / (e0 + e1 + e2);
        go[4] = e0 * rs; go[5] = e1 * rs; go[6] = e2 * rs;
    }
#pragma unroll
    for (int j = 0; j < 7; j++) out[pix * 7 + j] = go[j];

    float pr[3];
#pragma unroll
    for (int j = 0; j < 3; j++) pr[j] = bp[j];
    for (int c = 0; c < 8; c++) {
        float x = row[64 + c];
#pragma unroll
        for (int j = 0; j < 3; j++) pr[j] += x * wp[c * 3 + j];
    }
    {
        float m = fmaxf(pr[0], fmaxf(pr[1], pr[2]));
        float e0 = __expf(pr[0] - m), e1 = __expf(pr[1] - m), e2 = __expf(pr[2] - m);
        float rs = 1.0f / (e0 + e1 + e2);
        out[HW * 7 + pix * 3 + 0] = e0 * rs;
        out[HW * 7 + pix * 3 + 1] = e1 * rs;
        out[HW * 7 + pix * 3 + 2] = e2 * rs;
    }
}

// ---------------------------------------------------------------------------
extern "C" void kernel_launch(void* const* d_in, const int* in_sizes, int n_in,
                              void* d_out, int out_size) {
    const float* f_t     = (const float*)d_in[0];
    const float* gamma_0 = (const float*)d_in[1];
    const float* gamma_t = (const float*)d_in[2];
    const float* pi_t    = (const float*)d_in[3];
    const float* w_mlp1  = (const float*)d_in[4];
    const float* b_mlp1  = (const float*)d_in[5];
    const float* w_mlp2  = (const float*)d_in[6];
    const float* b_mlp2  = (const float*)d_in[7];
    const float* wq1     = (const float*)d_in[8];
    const float* bq1     = (const float*)d_in[9];
    const float* wk1     = (const float*)d_in[10];
    const float* bk1     = (const float*)d_in[11];
    const float* wv1     = (const float*)d_in[12];
    const float* bv1     = (const float*)d_in[13];
    const float* wq2     = (const float*)d_in[14];
    const float* bq2     = (const float*)d_in[15];
    const float* wk2     = (const float*)d_in[16];
    const float* bk2     = (const float*)d_in[17];
    const float* wv2     = (const float*)d_in[18];
    const float* bv2     = (const float*)d_in[19];
    const float* w_g     = (const float*)d_in[20];
    const float* b_g     = (const float*)d_in[21];
    const float* w_p     = (const float*)d_in[22];
    const float* b_p     = (const float*)d_in[23];
    float* out = (float*)d_out;

    float* base = nullptr;
    cudaGetSymbolAddress((void**)&base, g_scratch);
    float* q   = base;
    float* kv  = q   + HW * 72;
    float* qh1 = kv  + HW * 72;
    float* qh2 = qh1 + HW * 72;
    float* kp  = qh2 + HW * 72;
    float* vp  = kp  + HW * 72;
    float* o1  = vp  + HW * 72;
    float* gp  = o1  + HW * 72;

    const int attn_smem = (36 * KSTR) * 4 + (324 * 18) * 8 + (64 * SSTR + 64) * 4;
    cudaFuncSetAttribute(attn_kernel, cudaFuncAttributeMaxDynamicSharedMemorySize, attn_smem);

    mlp_pair_kernel<<<512, 288>>>(gamma_0, gamma_t, pi_t, f_t,
                                  w_mlp1, b_mlp1, w_mlp2, b_mlp2, q, kv);
    proj_quad_kernel<<<1024, 288>>>(q,  wq1, bq1, qh1,
                                    q,  wq2, bq2, qh2,
                                    kv, wk1, bk1, kp,
                                    kv, wv1, bv1, vp);
    attn_kernel<<<dim3(16, 16), 1024, attn_smem>>>(qh1, kp, vp, o1);
    proj_pair_kernel<<<512, 288>>>(o1, wk2, bk2, kp,
                                   o1, wv2, bv2, vp);
    attn_kernel<<<dim3(16, 16), 1024, attn_smem>>>(qh2, kp, vp, gp);
    head_split_kernel<<<64 + (HW * 72 + 255) / 256, 256>>>(gp, w_g, b_g, w_p, b_p, out);
}

// round 11
// speedup vs baseline: 1.2754x; 1.0377x over previous
#include <cuda_runtime.h>
#include <math.h>

#define HW     16384
#define IMG    128
#define TS     8
#define RAD    5
#define KW     11
#define HALO   18
#define NNB    121
#define SSTR   124
#define KSTR   325
#define SCALE  0.11785113019775793f  // 1/sqrt(72)

typedef unsigned long long ull;

__device__ float g_scratch[HW * 72 * 8];

__device__ __forceinline__ float gelu_exact(float x) {
    return 0.5f * x * (1.0f + erff(x * 0.70710678118654752f));
}
__device__ __forceinline__ unsigned bf2(float hi, float lo) {
    unsigned r;
    asm("cvt.rn.bf16x2.f32 %0, %1, %2;" : "=r"(r) : "f"(hi), "f"(lo));
    return r;
}
__device__ __forceinline__ float bf_lo(unsigned u) { return __uint_as_float(u << 16); }
__device__ __forceinline__ float bf_hi(unsigned u) { return __uint_as_float(u & 0xffff0000u); }

// ---------------------------------------------------------------------------
// Single GEMM body: Y = X@W + b. 64 px, 288 thr, 4px x 4outs.
// k processed in PAIRS: float2 x-loads + two float4 w-loads per 32 FMAs.
// ---------------------------------------------------------------------------
__device__ __forceinline__ void proj_body(const float* __restrict__ X,
                                          const float* __restrict__ W,
                                          const float* __restrict__ B,
                                          float* __restrict__ Y,
                                          int blk, char* smraw) {
    float* Xs = (float*)smraw;        // 64*72
    float* Ws = Xs + 64 * 72;         // 72*72
    float* bs = Ws + 72 * 72;         // 72
    const int tid = threadIdx.x;
    const int pix0 = blk * 64;

    for (int i = tid; i < 64 * 18; i += 288)
        ((float4*)Xs)[i] = ((const float4*)(X + pix0 * 72))[i];
    for (int i = tid; i < 72 * 18; i += 288)
        ((float4*)Ws)[i] = ((const float4*)W)[i];
    if (tid < 72) bs[tid] = B[tid];
    __syncthreads();

    const int og = tid % 18, pg = tid / 18;
    const int ob = og * 4, xb = pg * 4;

    float acc[4][4];
#pragma unroll
    for (int i = 0; i < 4; i++)
#pragma unroll
        for (int j = 0; j < 4; j++) acc[i][j] = 0.0f;

    for (int k = 0; k < 72; k += 2) {
        float2 x0 = *(const float2*)&Xs[(xb + 0) * 72 + k];
        float2 x1 = *(const float2*)&Xs[(xb + 1) * 72 + k];
        float2 x2 = *(const float2*)&Xs[(xb + 2) * 72 + k];
        float2 x3 = *(const float2*)&Xs[(xb + 3) * 72 + k];
        float4 wa = *(const float4*)&Ws[k * 72 + ob];
        float4 wb = *(const float4*)&Ws[(k + 1) * 72 + ob];
        acc[0][0] += x0.x * wa.x; acc[0][1] += x0.x * wa.y; acc[0][2] += x0.x * wa.z; acc[0][3] += x0.x * wa.w;
        acc[1][0] += x1.x * wa.x; acc[1][1] += x1.x * wa.y; acc[1][2] += x1.x * wa.z; acc[1][3] += x1.x * wa.w;
        acc[2][0] += x2.x * wa.x; acc[2][1] += x2.x * wa.y; acc[2][2] += x2.x * wa.z; acc[2][3] += x2.x * wa.w;
        acc[3][0] += x3.x * wa.x; acc[3][1] += x3.x * wa.y; acc[3][2] += x3.x * wa.z; acc[3][3] += x3.x * wa.w;
        acc[0][0] += x0.y * wb.x; acc[0][1] += x0.y * wb.y; acc[0][2] += x0.y * wb.z; acc[0][3] += x0.y * wb.w;
        acc[1][0] += x1.y * wb.x; acc[1][1] += x1.y * wb.y; acc[1][2] += x1.y * wb.z; acc[1][3] += x1.y * wb.w;
        acc[2][0] += x2.y * wb.x; acc[2][1] += x2.y * wb.y; acc[2][2] += x2.y * wb.z; acc[2][3] += x2.y * wb.w;
        acc[3][0] += x3.y * wb.x; acc[3][1] += x3.y * wb.y; acc[3][2] += x3.y * wb.z; acc[3][3] += x3.y * wb.w;
    }
#pragma unroll
    for (int i = 0; i < 4; i++) {
        float4 r;
        r.x = acc[i][0] + bs[ob + 0];
        r.y = acc[i][1] + bs[ob + 1];
        r.z = acc[i][2] + bs[ob + 2];
        r.w = acc[i][3] + bs[ob + 3];
        *(float4*)&Y[(pix0 + xb + i) * 72 + ob] = r;
    }
}

__global__ __launch_bounds__(288) void proj_quad_kernel(
        const float* __restrict__ X0, const float* __restrict__ W0, const float* __restrict__ B0, float* __restrict__ Y0,
        const float* __restrict__ X1, const float* __restrict__ W1, const float* __restrict__ B1, float* __restrict__ Y1,
        const float* __restrict__ X2, const float* __restrict__ W2, const float* __restrict__ B2, float* __restrict__ Y2,
        const float* __restrict__ X3, const float* __restrict__ W3, const float* __restrict__ B3, float* __restrict__ Y3) {
    __shared__ char smraw[(64 * 72 + 72 * 72 + 72) * 4];
    int g = blockIdx.x >> 8, blk = blockIdx.x & 255;
    const float *X, *W, *B;
    float* Y;
    if (g == 0)      { X = X0; W = W0; B = B0; Y = Y0; }
    else if (g == 1) { X = X1; W = W1; B = B1; Y = Y1; }
    else if (g == 2) { X = X2; W = W2; B = B2; Y = Y2; }
    else             { X = X3; W = W3; B = B3; Y = Y3; }
    proj_body(X, W, B, Y, blk, smraw);
}

__global__ __launch_bounds__(288) void proj_pair_kernel(
        const float* __restrict__ X0, const float* __restrict__ W0, const float* __restrict__ B0, float* __restrict__ Y0,
        const float* __restrict__ X1, const float* __restrict__ W1, const float* __restrict__ B1, float* __restrict__ Y1) {
    __shared__ char smraw[(64 * 72 + 72 * 72 + 72) * 4];
    int g = blockIdx.x >> 8, blk = blockIdx.x & 255;
    const float *X, *W, *B;
    float* Y;
    if (g == 0) { X = X0; W = W0; B = B0; Y = Y0; }
    else        { X = X1; W = W1; B = B1; Y = Y1; }
    proj_body(X, W, B, Y, blk, smraw);
}

// ---------------------------------------------------------------------------
// MLP (gelu) with fused concat (R7 exact)
// ---------------------------------------------------------------------------
template <int TAIL>
__device__ __forceinline__ void mlp_body(const float* __restrict__ g0,
                                         const float* __restrict__ gt,
                                         const float* __restrict__ tail,
                                         const float* __restrict__ W,
                                         const float* __restrict__ B,
                                         float* __restrict__ Y,
                                         int blk, char* smraw) {
    constexpr int DIN = 64 + TAIL;
    float* Xs = (float*)smraw;        // 64*DIN
    float* Ws = Xs + 64 * DIN;        // DIN*72
    float* bs = Ws + DIN * 72;        // 72
    const int tid = threadIdx.x;
    const int pix0 = blk * 64;

    for (int i = tid; i < 64 * 64; i += 288) {
        int p = i >> 6, c = i & 63;
        Xs[p * DIN + c] = g0[(pix0 + p) * 64 + c] + gt[(pix0 + p) * 64 + c];
    }
    for (int i = tid; i < 64 * TAIL; i += 288) {
        int p = i / TAIL, c = i - p * TAIL;
        Xs[p * DIN + 64 + c] = tail[(pix0 + p) * TAIL + c];
    }
    for (int i = tid; i < DIN * 18; i += 288)
        ((float4*)Ws)[i] = ((const float4*)W)[i];
    if (tid < 72) bs[tid] = B[tid];
    __syncthreads();

    const int og = tid % 18, pg = tid / 18;
    const int ob = og * 4, xb = pg * 4;

    float acc[4][4];
#pragma unroll
    for (int i = 0; i < 4; i++)
#pragma unroll
        for (int j = 0; j < 4; j++) acc[i][j] = 0.0f;

    for (int k = 0; k < DIN; k++) {
        float x0 = Xs[(xb + 0) * DIN + k];
        float x1 = Xs[(xb + 1) * DIN + k];
        float x2 = Xs[(xb + 2) * DIN + k];
        float x3 = Xs[(xb + 3) * DIN + k];
        float4 w = *(const float4*)&Ws[k * 72 + ob];
        acc[0][0] += x0 * w.x; acc[0][1] += x0 * w.y; acc[0][2] += x0 * w.z; acc[0][3] += x0 * w.w;
        acc[1][0] += x1 * w.x; acc[1][1] += x1 * w.y; acc[1][2] += x1 * w.z; acc[1][3] += x1 * w.w;
        acc[2][0] += x2 * w.x; acc[2][1] += x2 * w.y; acc[2][2] += x2 * w.z; acc[2][3] += x2 * w.w;
        acc[3][0] += x3 * w.x; acc[3][1] += x3 * w.y; acc[3][2] += x3 * w.z; acc[3][3] += x3 * w.w;
    }
#pragma unroll
    for (int i = 0; i < 4; i++) {
        float4 r;
        r.x = gelu_exact(acc[i][0] + bs[ob + 0]);
        r.y = gelu_exact(acc[i][1] + bs[ob + 1]);
        r.z = gelu_exact(acc[i][2] + bs[ob + 2]);
        r.w = gelu_exact(acc[i][3] + bs[ob + 3]);
        *(float4*)&Y[(pix0 + xb + i) * 72 + ob] = r;
    }
}

__global__ __launch_bounds__(288) void mlp_pair_kernel(const float* __restrict__ g0,
                                                       const float* __restrict__ gt,
                                                       const float* __restrict__ pi,
                                                       const float* __restrict__ f,
                                                       const float* __restrict__ W1,
                                                       const float* __restrict__ B1,
                                                       const float* __restrict__ W2,
                                                       const float* __restrict__ B2,
                                                       float* __restrict__ Yq,
                                                       float* __restrict__ Ykv) {
    __shared__ char smraw[(64 * 72 + 72 * 72 + 72) * 4];
    if (blockIdx.x < 256) mlp_body<8>(g0, gt, pi, W1, B1, Yq,  blockIdx.x, smraw);
    else                  mlp_body<3>(g0, gt, f,  W2, B2, Ykv, blockIdx.x - 256, smraw);
}

// ---------------------------------------------------------------------------
// Attention (R7 exact, frozen): 8x8 tile, 512 threads.
// ---------------------------------------------------------------------------
__global__ __launch_bounds__(512) void attn_kernel(const float* __restrict__ Q,
                                                   const float* __restrict__ Kp,
                                                   const float* __restrict__ Vp,
                                                   float* __restrict__ O) {
    extern __shared__ char smraw[];
    unsigned* Ksh = (unsigned*)smraw;            // 36 * KSTR  (bf16x2 per entry)
    ull*      Vsh = (ull*)(Ksh + 36 * KSTR);     // 324 * 18   (bf16x4 per entry)
    float*    S   = (float*)(Vsh + 324 * 18);    // 64 * SSTR
    float*    red = S + 64 * SSTR;               // 64

    const int tid = threadIdx.x;
    const int tx = blockIdx.x, ty = blockIdx.y;
    const int ox = tx * TS - RAD, oy = ty * TS - RAD;

    for (int i = tid; i < HALO * HALO * 18; i += 512) {
        int cell = i / 18, j = i - cell * 18;
        int hy = cell / HALO, hx = cell - hy * HALO;
        int gy = oy + hy, gx = ox + hx;
        float4 kv = make_float4(0.f, 0.f, 0.f, 0.f);
        float4 vv = kv;
        if ((unsigned)gy < IMG && (unsigned)gx < IMG) {
            int base = (gy * IMG + gx) * 18;
            kv = __ldg((const float4*)Kp + base + j);
            vv = __ldg((const float4*)Vp + base + j);
        }
        Ksh[(2 * j + 0) * KSTR + cell] = bf2(kv.y, kv.x);
        Ksh[(2 * j + 1) * KSTR + cell] = bf2(kv.w, kv.z);
        unsigned v01 = bf2(vv.y, vv.x);
        unsigned v23 = bf2(vv.w, vv.z);
        Vsh[cell * 18 + j] = ((ull)v23 << 32) | (ull)v01;
    }
    __syncthreads();

    const int p = tid >> 3, sub = tid & 7;
    const int py = p >> 3, px = p & 7;
    const int gy = ty * TS + py, gx = tx * TS + px;

    // ---- phase A: scores ----
    {
        float q[72];
        const float4* qr = (const float4*)(Q + (gy * IMG + gx) * 72);
#pragma unroll
        for (int jj = 0; jj < 18; jj++) {
            float4 t = __ldg(qr + jj);
            q[4 * jj + 0] = t.x; q[4 * jj + 1] = t.y;
            q[4 * jj + 2] = t.z; q[4 * jj + 3] = t.w;
        }
        for (int n = sub; n < NNB; n += 8) {
            int qy = n / 11;
            int qx = n - qy * 11;
            int ny = gy + qy - RAD, nx = gx + qx - RAD;
            float s = -INFINITY;
            if ((unsigned)ny < IMG && (unsigned)nx < IMG) {
                const unsigned* kc = Ksh + (py + qy) * HALO + (px + qx);
                float a0 = 0.f, a1 = 0.f, a2 = 0.f, a3 = 0.f;
#pragma unroll
                for (int j2 = 0; j2 < 36; j2 += 2) {
                    unsigned u0 = kc[(j2 + 0) * KSTR];
                    unsigned u1 = kc[(j2 + 1) * KSTR];
                    a0 = fmaf(q[2 * j2 + 0], bf_lo(u0), a0);
                    a1 = fmaf(q[2 * j2 + 1], bf_hi(u0), a1);
                    a2 = fmaf(q[2 * j2 + 2], bf_lo(u1), a2);
                    a3 = fmaf(q[2 * j2 + 3], bf_hi(u1), a3);
                }
                s = (a0 + a1 + a2 + a3) * SCALE;
            }
            S[p * SSTR + n] = s;
        }
    }
    __syncwarp();

    // ---- softmax: 8-lane cooperative ----
    {
        float* row = S + p * SSTR;
        float m = -INFINITY;
        for (int n = sub; n < NNB; n += 8) m = fmaxf(m, row[n]);
        m = fmaxf(m, __shfl_xor_sync(0xffffffffu, m, 1));
        m = fmaxf(m, __shfl_xor_sync(0xffffffffu, m, 2));
        m = fmaxf(m, __shfl_xor_sync(0xffffffffu, m, 4));
        float sum = 0.f;
        for (int n = sub; n < NNB; n += 8) {
            float e = __expf(row[n] - m);
            row[n] = e;
            sum += e;
        }
        sum += __shfl_xor_sync(0xffffffffu, sum, 1);
        sum += __shfl_xor_sync(0xffffffffu, sum, 2);
        sum += __shfl_xor_sync(0xffffffffu, sum, 4);
        if (sub == 0) red[p] = 1.0f / sum;
    }
    __syncthreads();

    // ---- phase B: attn @ V ----
    for (int u = tid; u < 64 * 18; u += 512) {
        int pp = u / 18, j = u - pp * 18;
        int ppy = pp >> 3, ppx = pp & 7;
        const float* arow = S + pp * SSTR;
        float c0 = 0.f, c1 = 0.f, c2 = 0.f, c3 = 0.f;
#pragma unroll 1
        for (int dy = 0; dy < KW; dy++) {
            const ull* vb = Vsh + (((ppy + dy) * HALO) + ppx) * 18 + j;
            const float* ar = arow + dy * KW;
#pragma unroll
            for (int dx = 0; dx < KW; dx++) {
                float a = ar[dx];
                ull v = vb[dx * 18];
                unsigned u0 = (unsigned)v;
                unsigned u1 = (unsigned)(v >> 32);
                c0 = fmaf(a, bf_lo(u0), c0);
                c1 = fmaf(a, bf_hi(u0), c1);
                c2 = fmaf(a, bf_lo(u1), c2);
                c3 = fmaf(a, bf_hi(u1), c3);
            }
        }
        float r = red[pp];
        float4 res = make_float4(c0 * r, c1 * r, c2 * r, c3 * r);
        int ogy = ty * TS + ppy, ogx = tx * TS + ppx;
        ((float4*)O)[(ogy * IMG + ogx) * 18 + j] = res;
    }
}

// ---------------------------------------------------------------------------
// head (blocks 0..63) + split (blocks 64..)
// ---------------------------------------------------------------------------
__global__ __launch_bounds__(256) void head_split_kernel(const float* __restrict__ gp,
                                                         const float* __restrict__ WG,
                                                         const float* __restrict__ BG,
                                                         const float* __restrict__ WP,
                                                         const float* __restrict__ BP,
                                                         float* __restrict__ out) {
    const int tid = threadIdx.x;
    if (blockIdx.x >= 64) {
        int i = (blockIdx.x - 64) * 256 + tid;
        if (i < HW * 72) {
            int pix = i / 72, c = i - pix * 72;
            float v = gp[i];
            if (c < 64) out[HW * 10 + pix * 64 + c] = v;
            else        out[HW * 74 + pix * 8 + (c - 64)] = v;
        }
        return;
    }
    __shared__ float wg[64 * 7];
    __shared__ float bg[7];
    __shared__ float wp[24];
    __shared__ float bp[3];
    for (int i = tid; i < 448; i += 256) wg[i] = WG[i];
    if (tid < 7)  bg[tid] = BG[tid];
    if (tid < 24) wp[tid] = WP[tid];
    if (tid < 3)  bp[tid] = BP[tid];
    __syncthreads();

    int pix = blockIdx.x * 256 + tid;
    const float* row = gp + pix * 72;

    float gr[7];
#pragma unroll
    for (int j = 0; j < 7; j++) gr[j] = bg[j];
    for (int c = 0; c < 64; c++) {
        float x = row[c];
#pragma unroll
        for (int j = 0; j < 7; j++) gr[j] += x * wg[c * 7 + j];
    }
    float go[7];
#pragma unroll
    for (int j = 0; j < 4; j++) go[j] = 1.0f / (1.0f + __expf(-gr[j]));
    {
        float m = fmaxf(gr[4], fmaxf(gr[5], gr[6]));
        float e0 = __expf(gr[4] - m), e1 = __expf(gr[5] - m), e2 = __expf(gr[6] - m);
        float rs = 1.0f / (e0 + e1 + e2);
        go[4] = e0 * rs; go[5] = e1 * rs; go[6] = e2 * rs;
    }
#pragma unroll
    for (int j = 0; j < 7; j++) out[pix * 7 + j] = go[j];

    float pr[3];
#pragma unroll
    for (int j = 0; j < 3; j++) pr[j] = bp[j];
    for (int c = 0; c < 8; c++) {
        float x = row[64 + c];
#pragma unroll
        for (int j = 0; j < 3; j++) pr[j] += x * wp[c * 3 + j];
    }
    {
        float m = fmaxf(pr[0], fmaxf(pr[1], pr[2]));
        float e0 = __expf(pr[0] - m), e1 = __expf(pr[1] - m), e2 = __expf(pr[2] - m);
        float rs = 1.0f / (e0 + e1 + e2);
        out[HW * 7 + pix * 3 + 0] = e0 * rs;
        out[HW * 7 + pix * 3 + 1] = e1 * rs;
        out[HW * 7 + pix * 3 + 2] = e2 * rs;
    }
}

// ---------------------------------------------------------------------------
extern "C" void kernel_launch(void* const* d_in, const int* in_sizes, int n_in,
                              void* d_out, int out_size) {
    const float* f_t     = (const float*)d_in[0];
    const float* gamma_0 = (const float*)d_in[1];
    const float* gamma_t = (const float*)d_in[2];
    const float* pi_t    = (const float*)d_in[3];
    const float* w_mlp1  = (const float*)d_in[4];
    const float* b_mlp1  = (const float*)d_in[5];
    const float* w_mlp2  = (const float*)d_in[6];
    const float* b_mlp2  = (const float*)d_in[7];
    const float* wq1     = (const float*)d_in[8];
    const float* bq1     = (const float*)d_in[9];
    const float* wk1     = (const float*)d_in[10];
    const float* bk1     = (const float*)d_in[11];
    const float* wv1     = (const float*)d_in[12];
    const float* bv1     = (const float*)d_in[13];
    const float* wq2     = (const float*)d_in[14];
    const float* bq2     = (const float*)d_in[15];
    const float* wk2     = (const float*)d_in[16];
    const float* bk2     = (const float*)d_in[17];
    const float* wv2     = (const float*)d_in[18];
    const float* bv2     = (const float*)d_in[19];
    const float* w_g     = (const float*)d_in[20];
    const float* b_g     = (const float*)d_in[21];
    const float* w_p     = (const float*)d_in[22];
    const float* b_p     = (const float*)d_in[23];
    float* out = (float*)d_out;

    float* base = nullptr;
    cudaGetSymbolAddress((void**)&base, g_scratch);
    float* q   = base;
    float* kv  = q   + HW * 72;
    float* qh1 = kv  + HW * 72;
    float* qh2 = qh1 + HW * 72;
    float* kp  = qh2 + HW * 72;
    float* vp  = kp  + HW * 72;
    float* o1  = vp  + HW * 72;
    float* gp  = o1  + HW * 72;

    const int attn_smem = (36 * KSTR) * 4 + (324 * 18) * 8 + (64 * SSTR + 64) * 4;
    cudaFuncSetAttribute(attn_kernel, cudaFuncAttributeMaxDynamicSharedMemorySize, attn_smem);

    mlp_pair_kernel<<<512, 288>>>(gamma_0, gamma_t, pi_t, f_t,
                                  w_mlp1, b_mlp1, w_mlp2, b_mlp2, q, kv);
    proj_quad_kernel<<<1024, 288>>>(q,  wq1, bq1, qh1,
                                    q,  wq2, bq2, qh2,
                                    kv, wk1, bk1, kp,
                                    kv, wv1, bv1, vp);
    attn_kernel<<<dim3(16, 16), 512, attn_smem>>>(qh1, kp, vp, o1);
    proj_pair_kernel<<<512, 288>>>(o1, wk2, bk2, kp,
                                   o1, wv2, bv2, vp);
    attn_kernel<<<dim3(16, 16), 512, attn_smem>>>(qh2, kp, vp, gp);
    head_split_kernel<<<64 + (HW * 72 + 255) / 256, 256>>>(gp, w_g, b_g, w_p, b_p, out);
}